// round 1
// baseline (speedup 1.0000x reference)
#include <cuda_runtime.h>
#include <math.h>

#define NREG 9
#define NCH  31
#define SCRATCH_N (1 + NREG * NCH * 7)

// scratch[0] = global sum of target
// per (r,c), base = 1 + (r*NCH+c)*7 :
//   +0 St1, +1 St3, +2 Sxt3, +3 Syt3, +4 Sp3, +5 Sxp3, +6 Syp3
__device__ double g_scratch[SCRATCH_N];

__global__ void coml_zero_kernel() {
    int i = blockIdx.x * blockDim.x + threadIdx.x;
    if (i < SCRATCH_N) g_scratch[i] = 0.0;
}

__device__ __forceinline__ float warp_sum(float v) {
#pragma unroll
    for (int o = 16; o; o >>= 1) v += __shfl_down_sync(0xffffffffu, v, o);
    return v;
}

// One block per (row y, channel ch). 256 threads, 8 target floats/thread.
__global__ __launch_bounds__(256) void coml_main_kernel(
    const float* __restrict__ pred, const float* __restrict__ targ) {
    const int y   = blockIdx.x;
    const int ch  = blockIdx.y;
    const int tid = threadIdx.x;
    const size_t rowoff = ((size_t)ch << 22) + ((size_t)y << 11);
    const float* trow = targ + rowoff;

    int rb = -1, i0 = 0;
    if      (y >= 200  && y < 600)  { rb = 0; i0 = y - 200;  }
    else if (y >= 1000 && y < 1400) { rb = 1; i0 = y - 1000; }
    else if (y >= 1500 && y < 1900) { rb = 2; i0 = y - 1500; }

    // acc[0] = gsum; per col-band cb: base 1+cb*5 -> {t1, t3, syt3, p3, syp3}
    float acc[16];
#pragma unroll
    for (int k = 0; k < 16; k++) acc[k] = 0.0f;

    // ---- target row (always) ----
    const float4* t4 = (const float4*)trow;
    float4 a = t4[tid * 2];
    float4 b = t4[tid * 2 + 1];
    float vv[8] = {a.x, a.y, a.z, a.w, b.x, b.y, b.z, b.w};
    float gs = 0.0f;
#pragma unroll
    for (int e = 0; e < 8; e++) gs += vv[e];
    acc[0] = gs;

    if (rb >= 0) {
        const int x0 = tid * 8;
#pragma unroll
        for (int e = 0; e < 8; e++) {
            const int x = x0 + e;
            const float v  = vv[e];
            const float v3 = v * v * v;
            if (x >= 200 && x < 600) {
                acc[1] += v; acc[2] += v3; acc[3] += (float)(x - 200) * v3;
            } else if (x >= 1000 && x < 1400) {
                acc[6] += v; acc[7] += v3; acc[8] += (float)(x - 1000) * v3;
            } else if (x >= 1500 && x < 1900) {
                acc[11] += v; acc[12] += v3; acc[13] += (float)(x - 1500) * v3;
            }
        }
        // ---- predicted row segments (region rows only) ----
        const float* prow = pred + rowoff;
        for (int x = 200 + tid; x < 600; x += 256) {
            float p = prow[x]; float p3 = p * p * p;
            acc[4] += p3; acc[5] += (float)(x - 200) * p3;
        }
        for (int x = 1000 + tid; x < 1400; x += 256) {
            float p = prow[x]; float p3 = p * p * p;
            acc[9] += p3; acc[10] += (float)(x - 1000) * p3;
        }
        for (int x = 1500 + tid; x < 1900; x += 256) {
            float p = prow[x]; float p3 = p * p * p;
            acc[14] += p3; acc[15] += (float)(x - 1500) * p3;
        }
    }

    // ---- block reduction ----
    __shared__ float red[8][16];
    __shared__ float fin[16];
    const int lane = tid & 31, wid = tid >> 5;
#pragma unroll
    for (int k = 0; k < 16; k++) acc[k] = warp_sum(acc[k]);
    if (lane == 0) {
#pragma unroll
        for (int k = 0; k < 16; k++) red[wid][k] = acc[k];
    }
    __syncthreads();
    if (tid < 16) {
        float s = 0.0f;
#pragma unroll
        for (int w = 0; w < 8; w++) s += red[w][tid];
        fin[tid] = s;
    }
    __syncthreads();

    if (tid == 0) atomicAdd(&g_scratch[0], (double)fin[0]);
    if (rb >= 0 && tid < 21) {
        const int cb = tid / 7, f = tid % 7;
        const int base = 1 + ((rb * 3 + cb) * NCH + ch) * 7;
        const float* aa = &fin[1 + cb * 5];  // {t1, t3, syt3, p3, syp3}
        double v = 0.0;
        switch (f) {
            case 0: v = (double)aa[0]; break;                 // St1
            case 1: v = (double)aa[1]; break;                 // St3
            case 2: v = (double)i0 * (double)aa[1]; break;    // Sxt3 = i * row St3
            case 3: v = (double)aa[2]; break;                 // Syt3
            case 4: v = (double)aa[3]; break;                 // Sp3
            case 5: v = (double)i0 * (double)aa[3]; break;    // Sxp3 = i * row Sp3
            case 6: v = (double)aa[4]; break;                 // Syp3
        }
        atomicAdd(&g_scratch[base + f], v);
    }
}

__global__ void coml_final_kernel(float* __restrict__ out) {
    __shared__ double sred[512];
    const int tid = threadIdx.x;
    double term = 0.0;
    if (tid < NREG * NCH) {
        const int r = tid / NCH;
        const double* s = &g_scratch[1 + tid * 7];
        const double St1  = s[0], St3  = s[1], Sxt3 = s[2], Syt3 = s[3];
        const double Sp3  = s[4], Sxp3 = s[5], Syp3 = s[6];
        const double cxt = (St3 != 0.0) ? Sxt3 / St3 : 0.0;
        const double cyt = (St3 != 0.0) ? Syt3 / St3 : 0.0;
        const double cxp = (Sp3 != 0.0) ? Sxp3 / Sp3 : 0.0;
        const double cyp = (Sp3 != 0.0) ? Syp3 / Sp3 : 0.0;
        const double dx = cxp - cxt, dy = cyp - cyt;
        const double nrm = sqrt(dx * dx + dy * dy);
        const double mean_t = g_scratch[0] / ((double)NCH * 2048.0 * 2048.0);
        const double w = (St1 / 160000.0) / mean_t;
        term = nrm * w;
        if (r == 4) term *= 5.0;  // FUNDAMENTAL_INDEX * FUNDA_WEIGHT
    }
    sred[tid] = term;
    __syncthreads();
#pragma unroll
    for (int st = 256; st >= 1; st >>= 1) {
        if (tid < st) sred[tid] += sred[tid + st];
        __syncthreads();
    }
    if (tid == 0) out[0] = (float)(sred[0] / (double)(NREG * NCH));
}

extern "C" void kernel_launch(void* const* d_in, const int* in_sizes, int n_in,
                              void* d_out, int out_size) {
    const float* pred = (const float*)d_in[0];
    const float* targ = (const float*)d_in[1];
    coml_zero_kernel<<<(SCRATCH_N + 255) / 256, 256>>>();
    dim3 grid(2048, NCH);
    coml_main_kernel<<<grid, 256>>>(pred, targ);
    coml_final_kernel<<<1, 512>>>((float*)d_out);
}

// round 2
// speedup vs baseline: 1.1889x; 1.1889x over previous
#include <cuda_runtime.h>
#include <math.h>

#define NCH  31
#define NREG 9
#define RPB  32
#define SCRATCH_N (1 + NREG * NCH * 7)

// scratch[0] = global sum of target
// per (r,c), base = 1 + (r*NCH+c)*7 : {St1, St3, Sxt3, Syt3, Sp3, Sxp3, Syp3}
__device__ double g_scratch[SCRATCH_N];

__device__ __forceinline__ float warp_sum(float v) {
#pragma unroll
    for (int o = 16; o; o >>= 1) v += __shfl_down_sync(0xffffffffu, v, o);
    return v;
}

// One block per (32-row group, channel). 256 threads, float4 streaming.
// Band boundaries guarantee a 32-row group overlaps at most ONE row band.
__global__ __launch_bounds__(256) void coml_main_kernel(
    const float* __restrict__ pred, const float* __restrict__ targ) {
    const int ch  = blockIdx.y;
    const int y0  = blockIdx.x * RPB;
    const int tid = threadIdx.x;
    const size_t chbase = ((size_t)ch << 22);

    // acc[0] = gsum; per col-band cb, base 1+cb*7: {t1, t3, xt3, yt3, p3, xp3, yp3}
    float acc[22];
#pragma unroll
    for (int k = 0; k < 22; k++) acc[k] = 0.0f;

    for (int rr = 0; rr < RPB; rr++) {
        const int y = y0 + rr;
        const float* trow = targ + chbase + ((size_t)y << 11);
        const float4 a = ((const float4*)trow)[tid * 2];
        const float4 b = ((const float4*)trow)[tid * 2 + 1];
        const float vv[8] = {a.x, a.y, a.z, a.w, b.x, b.y, b.z, b.w};
        float gs = 0.0f;
#pragma unroll
        for (int e = 0; e < 8; e++) gs += vv[e];
        acc[0] += gs;

        int rb, i0;
        if      (y >= 200  && y < 600)  { rb = 0; i0 = y - 200;  }
        else if (y >= 1000 && y < 1400) { rb = 1; i0 = y - 1000; }
        else if (y >= 1500 && y < 1900) { rb = 2; i0 = y - 1500; }
        else continue;
        const float i0f = (float)i0;

        // target region stats (thread's 8 columns are fixed across rows)
        const int x0 = tid * 8;
#pragma unroll
        for (int e = 0; e < 8; e++) {
            const int x = x0 + e;
            const float v = vv[e], v3 = v * v * v;
            if (x >= 200 && x < 600) {
                acc[1] += v; acc[2] += v3; acc[3] += i0f * v3; acc[4] += (float)(x - 200) * v3;
            } else if (x >= 1000 && x < 1400) {
                acc[8] += v; acc[9] += v3; acc[10] += i0f * v3; acc[11] += (float)(x - 1000) * v3;
            } else if (x >= 1500 && x < 1900) {
                acc[15] += v; acc[16] += v3; acc[17] += i0f * v3; acc[18] += (float)(x - 1500) * v3;
            }
        }

        // predicted region segments, float4-vectorized (3 x 100 float4)
        const float* prow = pred + chbase + ((size_t)y << 11);
        if (tid < 100) {
            const float4 p = ((const float4*)(prow + 200))[tid];
            const float pe[4] = {p.x, p.y, p.z, p.w};
#pragma unroll
            for (int e = 0; e < 4; e++) {
                const float q = pe[e], q3 = q * q * q;
                acc[5] += q3; acc[6] += i0f * q3; acc[7] += (float)(tid * 4 + e) * q3;
            }
        } else if (tid < 200) {
            const int j = tid - 100;
            const float4 p = ((const float4*)(prow + 1000))[j];
            const float pe[4] = {p.x, p.y, p.z, p.w};
#pragma unroll
            for (int e = 0; e < 4; e++) {
                const float q = pe[e], q3 = q * q * q;
                acc[12] += q3; acc[13] += i0f * q3; acc[14] += (float)(j * 4 + e) * q3;
            }
        } else {
            const int j = tid - 200;  // 0..55
            const float4 p = ((const float4*)(prow + 1500))[j];
            const float pe[4] = {p.x, p.y, p.z, p.w};
#pragma unroll
            for (int e = 0; e < 4; e++) {
                const float q = pe[e], q3 = q * q * q;
                acc[19] += q3; acc[20] += i0f * q3; acc[21] += (float)(j * 4 + e) * q3;
            }
        }
        if (tid < 44) {  // remaining float4s of segment 2: j = 56..99
            const int j = 56 + tid;
            const float4 p = ((const float4*)(prow + 1500))[j];
            const float pe[4] = {p.x, p.y, p.z, p.w};
#pragma unroll
            for (int e = 0; e < 4; e++) {
                const float q = pe[e], q3 = q * q * q;
                acc[19] += q3; acc[20] += i0f * q3; acc[21] += (float)(j * 4 + e) * q3;
            }
        }
    }

    // ---- one block-level reduction per block ----
    __shared__ float red[8][22];
    const int lane = tid & 31, wid = tid >> 5;
#pragma unroll
    for (int k = 0; k < 22; k++) acc[k] = warp_sum(acc[k]);
    if (lane == 0) {
#pragma unroll
        for (int k = 0; k < 22; k++) red[wid][k] = acc[k];
    }
    __syncthreads();
    if (tid < 22) {
        float s = 0.0f;
#pragma unroll
        for (int w = 0; w < 8; w++) s += red[w][tid];
        if (tid == 0) {
            atomicAdd(&g_scratch[0], (double)s);
        } else {
            // block's (single possible) row band
            const int ylo = y0, yhi = y0 + RPB - 1;
            int rb = -1;
            if      (yhi >= 200  && ylo < 600)  rb = 0;
            else if (yhi >= 1000 && ylo < 1400) rb = 1;
            else if (yhi >= 1500 && ylo < 1900) rb = 2;
            if (rb >= 0) {
                const int k = tid - 1, cb = k / 7, f = k % 7;
                const int r = rb * 3 + cb;
                atomicAdd(&g_scratch[1 + (r * NCH + ch) * 7 + f], (double)s);
            }
        }
    }
}

__global__ void coml_final_kernel(float* __restrict__ out) {
    __shared__ double sred[512];
    const int tid = threadIdx.x;
    const double mean_t = g_scratch[0] / ((double)NCH * 2048.0 * 2048.0);
    double term = 0.0;
    if (tid < NREG * NCH) {
        const int r = tid / NCH;
        const double* s = &g_scratch[1 + tid * 7];
        const double St1  = s[0], St3  = s[1], Sxt3 = s[2], Syt3 = s[3];
        const double Sp3  = s[4], Sxp3 = s[5], Syp3 = s[6];
        const double cxt = (St3 != 0.0) ? Sxt3 / St3 : 0.0;
        const double cyt = (St3 != 0.0) ? Syt3 / St3 : 0.0;
        const double cxp = (Sp3 != 0.0) ? Sxp3 / Sp3 : 0.0;
        const double cyp = (Sp3 != 0.0) ? Syp3 / Sp3 : 0.0;
        const double dx = cxp - cxt, dy = cyp - cyt;
        const double nrm = sqrt(dx * dx + dy * dy);
        const double w = (St1 / 160000.0) / mean_t;
        term = nrm * w;
        if (r == 4) term *= 5.0;  // FUNDAMENTAL_INDEX weighting
    }
    sred[tid] = term;
    __syncthreads();
    // all scratch reads complete -> self-clean for the next graph replay
    for (int i = tid; i < SCRATCH_N; i += 512) g_scratch[i] = 0.0;
#pragma unroll
    for (int st = 256; st >= 1; st >>= 1) {
        if (tid < st) sred[tid] += sred[tid + st];
        __syncthreads();
    }
    if (tid == 0) out[0] = (float)(sred[0] / (double)(NREG * NCH));
}

extern "C" void kernel_launch(void* const* d_in, const int* in_sizes, int n_in,
                              void* d_out, int out_size) {
    const float* pred = (const float*)d_in[0];
    const float* targ = (const float*)d_in[1];
    dim3 grid(2048 / RPB, NCH);
    coml_main_kernel<<<grid, 256>>>(pred, targ);
    coml_final_kernel<<<1, 512>>>((float*)d_out);
}

// round 3
// speedup vs baseline: 1.8087x; 1.5214x over previous
#include <cuda_runtime.h>
#include <math.h>

#define NCH  31
#define NREG 9
#define RPB  32
#define GX   (2048 / RPB)
#define NBLK (GX * NCH)
#define SCRATCH_N (1 + NREG * NCH * 7)

// scratch[0] = global target sum; per (r,c): {St1, St3, Sxt3, Syt3, Sp3, Sxp3, Syp3}
__device__ double g_scratch[SCRATCH_N];
__device__ unsigned int g_cnt = 0;

__device__ __forceinline__ float wsumf(float v) {
#pragma unroll
    for (int o = 16; o; o >>= 1) v += __shfl_down_sync(0xffffffffu, v, o);
    return v;
}
__device__ __forceinline__ double wsumd(double v) {
#pragma unroll
    for (int o = 16; o; o >>= 1) v += __shfl_down_sync(0xffffffffu, v, o);
    return v;
}

__global__ __launch_bounds__(512) void coml_kernel(
    const float* __restrict__ pred, const float* __restrict__ targ,
    float* __restrict__ out) {
    const int ch  = blockIdx.y;
    const int y0  = blockIdx.x * RPB;
    const int tid = threadIdx.x;
    const int lane = tid & 31, wid = tid >> 5;

    // block row-band (a 32-row group overlaps at most one band; gaps >= 100)
    const int yhi = y0 + RPB - 1;
    int rbm = -1, ylo_b = 0;
    if      (yhi >= 200  && y0 < 600)  { rbm = 0; ylo_b = 200;  }
    else if (yhi >= 1000 && y0 < 1400) { rbm = 1; ylo_b = 1000; }
    else if (yhi >= 1500 && y0 < 1900) { rbm = 2; ylo_b = 1500; }

    // thread col-band (float4 index == tid; edges all multiples of 4)
    int cb = -1, bxs = 0;
    if      (tid >= 50  && tid < 150) { cb = 0; bxs = 50;  }
    else if (tid >= 250 && tid < 350) { cb = 1; bxs = 250; }
    else if (tid >= 375 && tid < 475) { cb = 2; bxs = 375; }
    const float offb = (float)((tid - bxs) * 4);

    const size_t base4 = (((size_t)ch << 22) + ((size_t)y0 << 11)) >> 2;
    const float4* tp = (const float4*)targ + base4 + tid;
    const float4* pp = (const float4*)pred + base4 + tid;

    float gsum = 0.f, t1 = 0.f, t3 = 0.f, xt3 = 0.f, yt3 = 0.f;
    float q3a = 0.f, xp3 = 0.f, yp3 = 0.f;

    if (rbm >= 0 && cb >= 0) {
#pragma unroll 4
        for (int rr = 0; rr < RPB; rr++) {
            const float4 t = tp[rr * 512];
            gsum += (t.x + t.y) + (t.z + t.w);
            const int y = y0 + rr;
            if ((unsigned)(y - ylo_b) < 400u) {
                const float i0f = (float)(y - ylo_b);
                const float s1 = (t.x + t.y) + (t.z + t.w);
                t1 += s1;
                const float a3 = t.x*t.x*t.x, b3 = t.y*t.y*t.y;
                const float c3 = t.z*t.z*t.z, d3 = t.w*t.w*t.w;
                const float s3 = (a3 + b3) + (c3 + d3);
                t3 += s3;
                xt3 = fmaf(i0f, s3, xt3);
                yt3 += fmaf(offb, s3, b3 + 2.f*c3 + 3.f*d3);
                const float4 p = pp[rr * 512];
                const float e3 = p.x*p.x*p.x, f3 = p.y*p.y*p.y;
                const float g3 = p.z*p.z*p.z, h3 = p.w*p.w*p.w;
                const float sp = (e3 + f3) + (g3 + h3);
                q3a += sp;
                xp3 = fmaf(i0f, sp, xp3);
                yp3 += fmaf(offb, sp, f3 + 2.f*g3 + 3.f*h3);
            }
        }
    } else {
        // pure streaming: gsum only, deep unroll for MLP
#pragma unroll 8
        for (int rr = 0; rr < RPB; rr++) {
            const float4 t = tp[rr * 512];
            gsum += (t.x + t.y) + (t.z + t.w);
        }
    }

    // ---- block reduction: stage stat-major, 22 contiguous range sums ----
    __shared__ float sh[8 * 512];
    sh[0*512 + tid] = gsum;
    sh[1*512 + tid] = t1;
    sh[2*512 + tid] = t3;
    sh[3*512 + tid] = xt3;
    sh[4*512 + tid] = yt3;
    sh[5*512 + tid] = q3a;
    sh[6*512 + tid] = xp3;
    sh[7*512 + tid] = yp3;
    __syncthreads();

    for (int item = wid; item < 22; item += 16) {
        int k, lo, hi, b = -1;
        if (item == 0) { k = 0; lo = 0; hi = 512; }
        else {
            b = (item - 1) / 7;
            const int s = (item - 1) % 7;
            k = 1 + s;
            lo = (b == 0) ? 50 : (b == 1) ? 250 : 375;
            hi = lo + 100;
        }
        float s = 0.f;
        for (int i = lo + lane; i < hi; i += 32) s += sh[k * 512 + i];
        s = wsumf(s);
        if (lane == 0) {
            if (item == 0) atomicAdd(&g_scratch[0], (double)s);
            else if (rbm >= 0) {
                const int st = (item - 1) % 7;
                const int r = rbm * 3 + b;
                atomicAdd(&g_scratch[1 + (r * NCH + ch) * 7 + st], (double)s);
            }
        }
    }

    // ---- last block computes the loss and resets scratch ----
    __threadfence();
    __shared__ unsigned int ticket;
    __syncthreads();
    if (tid == 0) ticket = atomicAdd(&g_cnt, 1u);
    __syncthreads();
    if (ticket == NBLK - 1) {
        volatile double* vs = g_scratch;
        const double mean_t = vs[0] / ((double)NCH * 2048.0 * 2048.0);
        double term = 0.0;
        if (tid < NREG * NCH) {
            const int r = tid / NCH;
            const double St1  = vs[1 + tid*7 + 0], St3  = vs[1 + tid*7 + 1];
            const double Sxt3 = vs[1 + tid*7 + 2], Syt3 = vs[1 + tid*7 + 3];
            const double Sp3  = vs[1 + tid*7 + 4], Sxp3 = vs[1 + tid*7 + 5];
            const double Syp3 = vs[1 + tid*7 + 6];
            const double cxt = (St3 != 0.0) ? Sxt3 / St3 : 0.0;
            const double cyt = (St3 != 0.0) ? Syt3 / St3 : 0.0;
            const double cxp = (Sp3 != 0.0) ? Sxp3 / Sp3 : 0.0;
            const double cyp = (Sp3 != 0.0) ? Syp3 / Sp3 : 0.0;
            const double dx = cxp - cxt, dy = cyp - cyt;
            term = sqrt(dx * dx + dy * dy) * ((St1 / 160000.0) / mean_t);
            if (r == 4) term *= 5.0;  // fundamental region weight
        }
        term = wsumd(term);
        __shared__ double wpart[16];
        if (lane == 0) wpart[wid] = term;
        __syncthreads();
        if (tid == 0) {
            double s = 0.0;
#pragma unroll
            for (int w = 0; w < 16; w++) s += wpart[w];
            out[0] = (float)(s / (double)(NREG * NCH));
            g_cnt = 0;
        }
        for (int i = tid; i < SCRATCH_N; i += 512) g_scratch[i] = 0.0;
    }
}

extern "C" void kernel_launch(void* const* d_in, const int* in_sizes, int n_in,
                              void* d_out, int out_size) {
    const float* pred = (const float*)d_in[0];
    const float* targ = (const float*)d_in[1];
    dim3 grid(GX, NCH);
    coml_kernel<<<grid, 512>>>(pred, targ, (float*)d_out);
}

// round 4
// speedup vs baseline: 1.8584x; 1.0275x over previous
#include <cuda_runtime.h>
#include <math.h>

#define NCH  31
#define NREG 9
#define RPB  16
#define GX   (2048 / RPB)
#define NBLK (GX * NCH)
#define SCRATCH_N (1 + NREG * NCH * 7)

// scratch[0] = global target sum; per (r,c): {St1, St3, Sxt3, Syt3, Sp3, Sxp3, Syp3}
__device__ double g_scratch[SCRATCH_N];
__device__ unsigned int g_cnt = 0;

__device__ __forceinline__ float wsumf(float v) {
#pragma unroll
    for (int o = 16; o; o >>= 1) v += __shfl_down_sync(0xffffffffu, v, o);
    return v;
}
__device__ __forceinline__ double wsumd(double v) {
#pragma unroll
    for (int o = 16; o; o >>= 1) v += __shfl_down_sync(0xffffffffu, v, o);
    return v;
}

__global__ __launch_bounds__(512) void coml_kernel(
    const float* __restrict__ pred, const float* __restrict__ targ,
    float* __restrict__ out) {
    const int ch  = blockIdx.y;
    const int y0  = blockIdx.x * RPB;
    const int tid = threadIdx.x;
    const int lane = tid & 31, wid = tid >> 5;

    // block row-band intersection (a 16-row group overlaps at most one band)
    int rbm = -1, bs = 0;
    if      (y0 < 600  && y0 + RPB > 200)  { rbm = 0; bs = 200;  }
    else if (y0 < 1400 && y0 + RPB > 1000) { rbm = 1; bs = 1000; }
    else if (y0 < 1900 && y0 + RPB > 1500) { rbm = 2; bs = 1500; }
    int rlo = 0, rhi = 0;
    if (rbm >= 0) {
        rlo = max(0, bs - y0);
        rhi = min(RPB, bs + 400 - y0);
    }

    // thread col-band (float4 index == tid; all edges multiples of 4)
    int cb = -1, bxs = 0;
    if      (tid >= 50  && tid < 150) { cb = 0; bxs = 50;  }
    else if (tid >= 250 && tid < 350) { cb = 1; bxs = 250; }
    else if (tid >= 375 && tid < 475) { cb = 2; bxs = 375; }
    const float offb = (float)((tid - bxs) * 4);

    const size_t base4 = (((size_t)ch << 22) + ((size_t)y0 << 11)) >> 2;
    const float4* tp = (const float4*)targ + base4 + tid;
    const float4* pp = (const float4*)pred + base4 + tid;

    float g0 = 0.f, g1 = 0.f;
    float t1 = 0.f, t3 = 0.f, xt3 = 0.f, yt3 = 0.f;
    float q3a = 0.f, xp3 = 0.f, yp3 = 0.f;

    if (rbm < 0) {
        // pure streaming block: full unroll, max MLP
#pragma unroll
        for (int rr = 0; rr < RPB; rr += 2) {
            const float4 a = tp[rr * 512];
            const float4 b = tp[(rr + 1) * 512];
            g0 += (a.x + a.y) + (a.z + a.w);
            g1 += (b.x + b.y) + (b.z + b.w);
        }
    } else {
        for (int rr = 0; rr < rlo; rr++) {
            const float4 a = tp[rr * 512];
            g0 += (a.x + a.y) + (a.z + a.w);
        }
        // branch-free band loop
#pragma unroll 4
        for (int rr = rlo; rr < rhi; rr++) {
            const float4 t = tp[rr * 512];
            const float s1 = (t.x + t.y) + (t.z + t.w);
            g0 += s1;
            if (cb >= 0) {
                const float i0f = (float)(y0 + rr - bs);
                t1 += s1;
                const float a3 = t.x*t.x*t.x, b3 = t.y*t.y*t.y;
                const float c3 = t.z*t.z*t.z, d3 = t.w*t.w*t.w;
                const float s3 = (a3 + b3) + (c3 + d3);
                t3 += s3;
                xt3 = fmaf(i0f, s3, xt3);
                yt3 += fmaf(offb, s3, b3 + 2.f*c3 + 3.f*d3);
                const float4 p = pp[rr * 512];
                const float e3 = p.x*p.x*p.x, f3 = p.y*p.y*p.y;
                const float g3 = p.z*p.z*p.z, h3 = p.w*p.w*p.w;
                const float sp = (e3 + f3) + (g3 + h3);
                q3a += sp;
                xp3 = fmaf(i0f, sp, xp3);
                yp3 += fmaf(offb, sp, f3 + 2.f*g3 + 3.f*h3);
            }
        }
        for (int rr = rhi; rr < RPB; rr++) {
            const float4 a = tp[rr * 512];
            g1 += (a.x + a.y) + (a.z + a.w);
        }
    }
    const float gsum = g0 + g1;

    // ---- block reduction: stage stat-major, 22 contiguous range sums ----
    __shared__ float sh[8 * 512];
    sh[0*512 + tid] = gsum;
    sh[1*512 + tid] = t1;
    sh[2*512 + tid] = t3;
    sh[3*512 + tid] = xt3;
    sh[4*512 + tid] = yt3;
    sh[5*512 + tid] = q3a;
    sh[6*512 + tid] = xp3;
    sh[7*512 + tid] = yp3;
    __syncthreads();

    for (int item = wid; item < 22; item += 16) {
        int k, lo, hi, b = -1;
        if (item == 0) { k = 0; lo = 0; hi = 512; }
        else {
            b = (item - 1) / 7;
            const int s = (item - 1) % 7;
            k = 1 + s;
            lo = (b == 0) ? 50 : (b == 1) ? 250 : 375;
            hi = lo + 100;
        }
        float s = 0.f;
        for (int i = lo + lane; i < hi; i += 32) s += sh[k * 512 + i];
        s = wsumf(s);
        if (lane == 0) {
            if (item == 0) atomicAdd(&g_scratch[0], (double)s);
            else if (rbm >= 0 && rhi > rlo) {
                const int st = (item - 1) % 7;
                const int r = rbm * 3 + b;
                atomicAdd(&g_scratch[1 + (r * NCH + ch) * 7 + st], (double)s);
            }
        }
    }

    // ---- last block computes the loss and resets scratch ----
    __threadfence();
    __shared__ unsigned int ticket;
    __syncthreads();
    if (tid == 0) ticket = atomicAdd(&g_cnt, 1u);
    __syncthreads();
    if (ticket == NBLK - 1) {
        __threadfence();
        volatile double* vs = g_scratch;
        const double mean_t = vs[0] / ((double)NCH * 2048.0 * 2048.0);
        double term = 0.0;
        if (tid < NREG * NCH) {
            const int r = tid / NCH;
            const double St1  = vs[1 + tid*7 + 0], St3  = vs[1 + tid*7 + 1];
            const double Sxt3 = vs[1 + tid*7 + 2], Syt3 = vs[1 + tid*7 + 3];
            const double Sp3  = vs[1 + tid*7 + 4], Sxp3 = vs[1 + tid*7 + 5];
            const double Syp3 = vs[1 + tid*7 + 6];
            const double cxt = (St3 != 0.0) ? Sxt3 / St3 : 0.0;
            const double cyt = (St3 != 0.0) ? Syt3 / St3 : 0.0;
            const double cxp = (Sp3 != 0.0) ? Sxp3 / Sp3 : 0.0;
            const double cyp = (Sp3 != 0.0) ? Syp3 / Sp3 : 0.0;
            const double dx = cxp - cxt, dy = cyp - cyt;
            term = sqrt(dx * dx + dy * dy) * ((St1 / 160000.0) / mean_t);
            if (r == 4) term *= 5.0;  // fundamental region weight
        }
        term = wsumd(term);
        __shared__ double wpart[16];
        if (lane == 0) wpart[wid] = term;
        __syncthreads();
        if (tid == 0) {
            double s = 0.0;
#pragma unroll
            for (int w = 0; w < 16; w++) s += wpart[w];
            out[0] = (float)(s / (double)(NREG * NCH));
            g_cnt = 0;
        }
        for (int i = tid; i < SCRATCH_N; i += 512) g_scratch[i] = 0.0;
    }
}

extern "C" void kernel_launch(void* const* d_in, const int* in_sizes, int n_in,
                              void* d_out, int out_size) {
    const float* pred = (const float*)d_in[0];
    const float* targ = (const float*)d_in[1];
    dim3 grid(GX, NCH);
    coml_kernel<<<grid, 512>>>(pred, targ, (float*)d_out);
}